// round 4
// baseline (speedup 1.0000x reference)
#include <cuda_runtime.h>
#include <math_constants.h>

#define B    32
#define T    336
#define C    7
#define NSH  5
#define NG   4
#define NF   140            // 4 groups * 5 * 7
#define OUTC 10
#define NWORK (B * C * NG)   // 896 worker blocks
#define NHEAD 21             // 20 dot blocks + 1 loss block
#define NDOT  (B * OUTC)     // 320

// offsets in d_out (floats): out[320] | dists[4480] | probs[4480] | loss[1]
#define OFF_OUT   0
#define OFF_DIST  320
#define OFF_PROB  (320 + B*NF)
#define OFF_LOSS  (320 + 2*B*NF)

__device__ int g_ctr  = 0;   // workers completed
__device__ int g_ctr2 = 0;   // head blocks completed

// ---------------------------------------------------------------------------
template<int L, int K>
__device__ __forceinline__ float sliding_min(const float* __restrict__ sx,
                                             const float* __restrict__ sw,
                                             int tid, float* __restrict__ rmin) {
    constexpr int TW = T - L + 1;
    const int j0 = tid * K;
    float m = CUDART_INF_F;

    if (j0 < TW) {
        float acc[K];
        float r[K + 1];
        #pragma unroll
        for (int k = 0; k < K; k++) { acc[k] = 0.f; r[k] = sx[j0 + k]; }
        r[K] = sx[j0 + K];

        #pragma unroll 4
        for (int l = 0; l < L; l++) {
            const float wv = sw[l];                 // broadcast
            #pragma unroll
            for (int k = 0; k < K; k++)
                acc[k] += fabsf(r[k] - wv);
            #pragma unroll
            for (int k = 0; k < K; k++) r[k] = r[k + 1];
            r[K] = sx[j0 + K + l + 1];              // one new value / step
        }

        m = acc[0];
        #pragma unroll
        for (int k = 1; k < K; k++)
            if (j0 + k < TW) m = fminf(m, acc[k]);
    }

    #pragma unroll
    for (int o = 16; o > 0; o >>= 1)
        m = fminf(m, __shfl_xor_sync(0xffffffffu, m, o));
    if ((tid & 31) == 0) rmin[tid >> 5] = m;
    __syncthreads();
    float mm = fminf(fminf(rmin[0], rmin[1]), fminf(rmin[2], rmin[3]));
    __syncthreads();
    return mm * (1.0f / (float)L);
}

// ---------------------------------------------------------------------------
// One fused kernel. grid.x = 896 workers + 21 head blocks, 128 threads.
//  worker bid<896 : bc = bid/4, g = (bid%4 + bid/4)%4 ; 5 shapelets inside
//  head   bid>=896: spin until all workers done, then 16 dots each / loss
// ---------------------------------------------------------------------------
__global__ __launch_bounds__(128, 8) void fused_kernel(
        const float* __restrict__ x,
        const float* __restrict__ w0,
        const float* __restrict__ w1,
        const float* __restrict__ w2,
        const float* __restrict__ w3,
        const float* __restrict__ Wout,
        float* __restrict__ d_out) {
    const int bid = blockIdx.x;
    const int tid = threadIdx.x;          // 128

    if (bid < NWORK) {
        // ================= WORKER =================
        const int bc = bid >> 2;
        const int g  = ((bid & 3) + bc) & 3;   // rotate groups across SMs
        const int b  = bc / C;
        const int ch = bc % C;

        __shared__ __align__(16) float sx[T + 8];
        __shared__ __align__(16) float sw[NSH * 168];
        __shared__ float red[8];

        // ---- inline normalization (one pass: sum + sumsq) ----
        const float* xrow = x + (size_t)b * T * C + ch;   // stride C over t
        float vals[3];
        float s = 0.f, ss = 0.f;
        #pragma unroll
        for (int i = 0; i < 3; i++) {
            int t = tid + i * 128;
            float v = (t < T) ? xrow[(size_t)t * C] : 0.f;
            vals[i] = v;
            s += v;
            ss += v * v;
        }
        #pragma unroll
        for (int o = 16; o > 0; o >>= 1) {
            s  += __shfl_xor_sync(0xffffffffu, s, o);
            ss += __shfl_xor_sync(0xffffffffu, ss, o);
        }
        if ((tid & 31) == 0) { red[tid >> 5] = s; red[4 + (tid >> 5)] = ss; }
        __syncthreads();
        const float stot  = red[0] + red[1] + red[2] + red[3];
        const float sstot = red[4] + red[5] + red[6] + red[7];
        const float mu  = stot * (1.0f / (float)T);
        const float var = (sstot - (float)T * mu * mu) * (1.0f / (float)(T - 1));
        const float inv = 1.0f / (sqrtf(fmaxf(var, 0.f)) + 1e-8f);

        #pragma unroll
        for (int i = 0; i < 3; i++) {
            int t = tid + i * 128;
            if (t < T) sx[t] = (vals[i] - mu) * inv;
        }
        if (tid < 8) sx[T + tid] = 0.f;   // pad for rolling overread

        // ---- load all 5 shapelet rows of (g, ch) ----
        const float* wg;
        int L;
        switch (g) {
            case 0:  L = 34;  wg = w0; break;
            case 1:  L = 68;  wg = w1; break;
            case 2:  L = 101; wg = w2; break;
            default: L = 168; wg = w3; break;
        }
        for (int i = tid; i < NSH * L; i += 128) {
            int nn = i / L, l = i % L;
            sw[nn * L + l] = wg[(size_t)(nn * C + ch) * L + l];
        }
        __syncthreads();

        for (int nn = 0; nn < NSH; nn++) {
            float dmin;
            const float* swn = sw + nn * L;
            switch (g) {
                case 0:  dmin = sliding_min<34, 3>(sx, swn, tid, red); break;
                case 1:  dmin = sliding_min<68, 3>(sx, swn, tid, red); break;
                case 2:  dmin = sliding_min<101, 2>(sx, swn, tid, red); break;
                default: dmin = sliding_min<168, 2>(sx, swn, tid, red); break;
            }
            if (tid == 0) {
                const int idx = b * NF + g * (NSH * C) + nn * C + ch;
                d_out[OFF_DIST + idx] = dmin;
                d_out[OFF_PROB + idx] = expf(-dmin * dmin);   // EPS_GATE = 1
            }
        }

        if (tid == 0) {
            __threadfence();
            atomicAdd(&g_ctr, 1);        // publish this block's results
        }
    } else {
        // ================= HEAD =================
        const int h = bid - NWORK;       // 0..20

        if (tid == 0) {
            while (atomicAdd(&g_ctr, 0) < NWORK) __nanosleep(64);
        }
        __syncthreads();
        __threadfence();                  // acquire published probs

        if (h < 20) {
            // 16 dots per block; warp w does 4 dots
            const int w   = tid >> 5;
            const int ln  = tid & 31;
            const float* probs = d_out + OFF_PROB;
            #pragma unroll
            for (int d = 0; d < 4; d++) {
                const int dot = h * 16 + w * 4 + d;     // < 320
                const int b = dot / OUTC;
                const int o = dot % OUTC;
                const float* p = probs + b * NF;
                const float* wv = Wout + o * NF;
                float v = 0.f;
                #pragma unroll
                for (int f = ln; f < NF; f += 32) v += p[f] * wv[f];
                #pragma unroll
                for (int off = 16; off > 0; off >>= 1)
                    v += __shfl_xor_sync(0xffffffffu, v, off);
                if (ln == 0) d_out[OFF_OUT + dot] = v;
            }
        } else {
            // loss = 0.1 * mean|Wout|
            __shared__ float sred[4];
            float v = 0.f;
            #pragma unroll
            for (int i = tid; i < OUTC * NF; i += 128) v += fabsf(Wout[i]);
            #pragma unroll
            for (int off = 16; off > 0; off >>= 1)
                v += __shfl_xor_sync(0xffffffffu, v, off);
            if ((tid & 31) == 0) sred[tid >> 5] = v;
            __syncthreads();
            if (tid == 0) {
                float tot = sred[0] + sred[1] + sred[2] + sred[3];
                d_out[OFF_LOSS] = 0.1f * tot / (float)(OUTC * NF);
            }
        }

        __syncthreads();
        if (tid == 0) {
            int v = atomicAdd(&g_ctr2, 1);
            if (v == NHEAD - 1) {
                // last head block: everyone has passed the spin; reset for
                // the next (deterministic) replay of this graph node.
                atomicExch(&g_ctr, 0);
                atomicExch(&g_ctr2, 0);
            }
        }
    }
}

// ---------------------------------------------------------------------------
extern "C" void kernel_launch(void* const* d_in, const int* in_sizes, int n_in,
                              void* d_out, int out_size) {
    const float* x    = (const float*)d_in[0];
    const float* w0   = (const float*)d_in[1];
    const float* w1   = (const float*)d_in[2];
    const float* w2   = (const float*)d_in[3];
    const float* w3   = (const float*)d_in[4];
    const float* Wout = (const float*)d_in[5];
    float* out = (float*)d_out;

    fused_kernel<<<NWORK + NHEAD, 128>>>(x, w0, w1, w2, w3, Wout, out);
}

// round 5
// speedup vs baseline: 1.0973x; 1.0973x over previous
#include <cuda_runtime.h>
#include <math_constants.h>

#define B    32
#define T    336
#define C    7
#define NSH  5
#define NG   4
#define NF   140            // 4 groups * 5 * 7
#define OUTC 10
#define NWORK (B * C * NG * NSH)   // 4480 worker blocks (one per bc,g,nn)
#define NHEAD 21                   // 20 dot blocks + 1 loss block

// offsets in d_out (floats): out[320] | dists[4480] | probs[4480] | loss[1]
#define OFF_OUT   0
#define OFF_DIST  320
#define OFF_PROB  (320 + B*NF)
#define OFF_LOSS  (320 + 2*B*NF)

__device__ int g_ctr  = 0;   // workers completed
__device__ int g_ctr2 = 0;   // head blocks completed

// ---------------------------------------------------------------------------
template<int L, int K>
__device__ __forceinline__ float sliding_min(const float* __restrict__ sx,
                                             const float* __restrict__ sw,
                                             int tid, float* __restrict__ rmin) {
    constexpr int TW = T - L + 1;
    const int j0 = tid * K;
    float m = CUDART_INF_F;

    if (j0 < TW) {
        float acc[K];
        float r[K + 1];
        #pragma unroll
        for (int k = 0; k < K; k++) { acc[k] = 0.f; r[k] = sx[j0 + k]; }
        r[K] = sx[j0 + K];

        #pragma unroll 4
        for (int l = 0; l < L; l++) {
            const float wv = sw[l];                 // broadcast
            #pragma unroll
            for (int k = 0; k < K; k++)
                acc[k] += fabsf(r[k] - wv);
            #pragma unroll
            for (int k = 0; k < K; k++) r[k] = r[k + 1];
            r[K] = sx[j0 + K + l + 1];              // one new value / step
        }

        m = acc[0];
        #pragma unroll
        for (int k = 1; k < K; k++)
            if (j0 + k < TW) m = fminf(m, acc[k]);
    }

    #pragma unroll
    for (int o = 16; o > 0; o >>= 1)
        m = fminf(m, __shfl_xor_sync(0xffffffffu, m, o));
    if ((tid & 31) == 0) rmin[tid >> 5] = m;
    __syncthreads();
    float mm = fminf(fminf(rmin[0], rmin[1]), fminf(rmin[2], rmin[3]));
    return mm * (1.0f / (float)L);
}

// ---------------------------------------------------------------------------
// Single launch. grid.x = 4480 workers + 21 head blocks, 128 threads.
//  worker: one (bc, g, nn) triple — round-3 granularity
//  head  : spins until all workers done, then 16 dots each / loss
// ---------------------------------------------------------------------------
__global__ __launch_bounds__(128, 8) void fused_kernel(
        const float* __restrict__ x,
        const float* __restrict__ w0,
        const float* __restrict__ w1,
        const float* __restrict__ w2,
        const float* __restrict__ w3,
        const float* __restrict__ Wout,
        float* __restrict__ d_out) {
    const int bid = blockIdx.x;
    const int tid = threadIdx.x;          // 128

    if (bid < NWORK) {
        // ================= WORKER =================
        // bid = (bc*4 + graw)*5 + nn ; rotate g by bc to mix lengths per wave
        const int nn   = bid % NSH;
        const int q    = bid / NSH;          // bc*4 + graw
        const int bc   = q >> 2;
        const int g    = ((q & 3) + bc) & 3;
        const int b    = bc / C;
        const int ch   = bc % C;

        __shared__ __align__(16) float sx[T + 8];
        __shared__ __align__(16) float sw[168];
        __shared__ float red[8];

        // ---- inline normalization (one pass: sum + sumsq) ----
        const float* xrow = x + (size_t)b * T * C + ch;   // stride C over t
        float vals[3];
        float s = 0.f, ss = 0.f;
        #pragma unroll
        for (int i = 0; i < 3; i++) {
            int t = tid + i * 128;
            float v = (t < T) ? xrow[(size_t)t * C] : 0.f;
            vals[i] = v;
            s += v;
            ss += v * v;
        }
        #pragma unroll
        for (int o = 16; o > 0; o >>= 1) {
            s  += __shfl_xor_sync(0xffffffffu, s, o);
            ss += __shfl_xor_sync(0xffffffffu, ss, o);
        }
        if ((tid & 31) == 0) { red[tid >> 5] = s; red[4 + (tid >> 5)] = ss; }
        __syncthreads();
        const float stot  = red[0] + red[1] + red[2] + red[3];
        const float sstot = red[4] + red[5] + red[6] + red[7];
        const float mu  = stot * (1.0f / (float)T);
        const float var = (sstot - (float)T * mu * mu) * (1.0f / (float)(T - 1));
        const float inv = 1.0f / (sqrtf(fmaxf(var, 0.f)) + 1e-8f);

        #pragma unroll
        for (int i = 0; i < 3; i++) {
            int t = tid + i * 128;
            if (t < T) sx[t] = (vals[i] - mu) * inv;
        }
        if (tid < 8) sx[T + tid] = 0.f;   // pad for rolling overread

        // ---- load the single shapelet row (nn, ch) of group g ----
        const float* wg;
        int L;
        switch (g) {
            case 0:  L = 34;  wg = w0; break;
            case 1:  L = 68;  wg = w1; break;
            case 2:  L = 101; wg = w2; break;
            default: L = 168; wg = w3; break;
        }
        const float* wrow = wg + (size_t)(nn * C + ch) * L;
        for (int i = tid; i < L; i += 128) sw[i] = wrow[i];
        __syncthreads();

        float dmin;
        switch (g) {
            case 0:  dmin = sliding_min<34, 3>(sx, sw, tid, red); break;   // tw=303
            case 1:  dmin = sliding_min<68, 3>(sx, sw, tid, red); break;   // tw=269
            case 2:  dmin = sliding_min<101, 2>(sx, sw, tid, red); break;  // tw=236
            default: dmin = sliding_min<168, 2>(sx, sw, tid, red); break;  // tw=169
        }

        if (tid == 0) {
            const int idx = b * NF + g * (NSH * C) + nn * C + ch;
            d_out[OFF_DIST + idx] = dmin;
            d_out[OFF_PROB + idx] = expf(-dmin * dmin);   // EPS_GATE = 1
            __threadfence();
            atomicAdd(&g_ctr, 1);        // publish this block's result
        }
    } else {
        // ================= HEAD =================
        const int h = bid - NWORK;       // 0..20

        if (tid == 0) {
            while (atomicAdd(&g_ctr, 0) < NWORK) __nanosleep(64);
        }
        __syncthreads();
        __threadfence();                  // acquire published probs

        if (h < 20) {
            // 16 dots per block; warp w does 4 dots
            const int w   = tid >> 5;
            const int ln  = tid & 31;
            const float* probs = d_out + OFF_PROB;
            #pragma unroll
            for (int d = 0; d < 4; d++) {
                const int dot = h * 16 + w * 4 + d;     // < 320
                const int b = dot / OUTC;
                const int o = dot % OUTC;
                const float* p = probs + b * NF;
                const float* wv = Wout + o * NF;
                float v = 0.f;
                #pragma unroll
                for (int f = ln; f < NF; f += 32) v += p[f] * wv[f];
                #pragma unroll
                for (int off = 16; off > 0; off >>= 1)
                    v += __shfl_xor_sync(0xffffffffu, v, off);
                if (ln == 0) d_out[OFF_OUT + dot] = v;
            }
        } else {
            // loss = 0.1 * mean|Wout|
            __shared__ float sred[4];
            float v = 0.f;
            #pragma unroll
            for (int i = tid; i < OUTC * NF; i += 128) v += fabsf(Wout[i]);
            #pragma unroll
            for (int off = 16; off > 0; off >>= 1)
                v += __shfl_xor_sync(0xffffffffu, v, off);
            if ((tid & 31) == 0) sred[tid >> 5] = v;
            __syncthreads();
            if (tid == 0) {
                float tot = sred[0] + sred[1] + sred[2] + sred[3];
                d_out[OFF_LOSS] = 0.1f * tot / (float)(OUTC * NF);
            }
        }

        __syncthreads();
        if (tid == 0) {
            int v = atomicAdd(&g_ctr2, 1);
            if (v == NHEAD - 1) {
                // last head block resets counters for the next graph replay
                atomicExch(&g_ctr, 0);
                atomicExch(&g_ctr2, 0);
            }
        }
    }
}

// ---------------------------------------------------------------------------
extern "C" void kernel_launch(void* const* d_in, const int* in_sizes, int n_in,
                              void* d_out, int out_size) {
    const float* x    = (const float*)d_in[0];
    const float* w0   = (const float*)d_in[1];
    const float* w1   = (const float*)d_in[2];
    const float* w2   = (const float*)d_in[3];
    const float* w3   = (const float*)d_in[4];
    const float* Wout = (const float*)d_in[5];
    float* out = (float*)d_out;

    fused_kernel<<<NWORK + NHEAD, 128>>>(x, w0, w1, w2, w3, Wout, out);
}

// round 6
// speedup vs baseline: 1.1361x; 1.0353x over previous
#include <cuda_runtime.h>
#include <math_constants.h>

#define B    32
#define T    336
#define C    7
#define NSH  5
#define NG   4
#define NF   140            // 4 groups * 5 * 7
#define OUTC 10
#define NWORK (B * C * NG * NSH)   // 4480 worker blocks (one per bc,g,nn)
#define NHEAD 21                   // 20 dot blocks + 1 loss block

// offsets in d_out (floats): out[320] | dists[4480] | probs[4480] | loss[1]
#define OFF_OUT   0
#define OFF_DIST  320
#define OFF_PROB  (320 + B*NF)
#define OFF_LOSS  (320 + 2*B*NF)

__device__ int g_ctr  = 0;   // workers completed
__device__ int g_ctr2 = 0;   // head blocks completed

// ---------------------------------------------------------------------------
// K=4 consecutive windows per thread, float4-vectorized inner loop.
// Per 4 l-steps: 1 LDS.128 (new x slab) + 1 LDS.128 (w, broadcast) + 16 FADD.
// ---------------------------------------------------------------------------
template<int L>
__device__ __forceinline__ float sliding_min4(const float* __restrict__ sx,
                                              const float* __restrict__ sw,
                                              int tid, float* __restrict__ rmin) {
    constexpr int TW  = T - L + 1;
    constexpr int LV  = L / 4;
    constexpr int REM = L % 4;
    const int j0 = tid * 4;                 // 16B-aligned window base
    float m = CUDART_INF_F;

    if (j0 < TW) {
        const float4* sx4 = reinterpret_cast<const float4*>(sx) + (j0 >> 2);
        const float4* sw4 = reinterpret_cast<const float4*>(sw);

        float4 lo = sx4[0];
        float4 hi = sx4[1];
        float a0 = 0.f, a1 = 0.f, a2 = 0.f, a3 = 0.f;

        #pragma unroll 2
        for (int lv = 0; lv < LV; lv++) {
            const float4 wv = sw4[lv];      // broadcast load
            const float x0 = lo.x, x1 = lo.y, x2 = lo.z, x3 = lo.w;
            const float x4 = hi.x, x5 = hi.y, x6 = hi.z;

            a0 += fabsf(x0 - wv.x); a1 += fabsf(x1 - wv.x);
            a2 += fabsf(x2 - wv.x); a3 += fabsf(x3 - wv.x);

            a0 += fabsf(x1 - wv.y); a1 += fabsf(x2 - wv.y);
            a2 += fabsf(x3 - wv.y); a3 += fabsf(x4 - wv.y);

            a0 += fabsf(x2 - wv.z); a1 += fabsf(x3 - wv.z);
            a2 += fabsf(x4 - wv.z); a3 += fabsf(x5 - wv.z);

            a0 += fabsf(x3 - wv.w); a1 += fabsf(x4 - wv.w);
            a2 += fabsf(x5 - wv.w); a3 += fabsf(x6 - wv.w);

            lo = hi;
            hi = sx4[lv + 2];               // aligned, in padded bounds
        }

        if (REM > 0) {
            // post-loop: lo = sx[j0+4LV .. +3], hi = sx[j0+4LV+4 .. +7]
            const float xs[7] = { lo.x, lo.y, lo.z, lo.w, hi.x, hi.y, hi.z };
            #pragma unroll
            for (int r = 0; r < REM; r++) {
                const float wv = sw[4 * LV + r];
                a0 += fabsf(xs[r]     - wv);
                a1 += fabsf(xs[r + 1] - wv);
                a2 += fabsf(xs[r + 2] - wv);
                a3 += fabsf(xs[r + 3] - wv);
            }
        }

        m = a0;
        if (j0 + 1 < TW) m = fminf(m, a1);
        if (j0 + 2 < TW) m = fminf(m, a2);
        if (j0 + 3 < TW) m = fminf(m, a3);
    }

    #pragma unroll
    for (int o = 16; o > 0; o >>= 1)
        m = fminf(m, __shfl_xor_sync(0xffffffffu, m, o));
    if ((tid & 31) == 0) rmin[tid >> 5] = m;
    __syncthreads();
    float mm = fminf(fminf(rmin[0], rmin[1]), fminf(rmin[2], rmin[3]));
    return mm * (1.0f / (float)L);
}

// ---------------------------------------------------------------------------
// Single launch. grid.x = 4480 workers + 21 head blocks, 128 threads.
// ---------------------------------------------------------------------------
__global__ __launch_bounds__(128, 8) void fused_kernel(
        const float* __restrict__ x,
        const float* __restrict__ w0,
        const float* __restrict__ w1,
        const float* __restrict__ w2,
        const float* __restrict__ w3,
        const float* __restrict__ Wout,
        float* __restrict__ d_out) {
    const int bid = blockIdx.x;
    const int tid = threadIdx.x;          // 128

    if (bid < NWORK) {
        // ================= WORKER =================
        const int nn = bid % NSH;
        const int q  = bid / NSH;            // bc*4 + graw
        const int bc = q >> 2;
        const int g  = ((q & 3) + bc) & 3;   // rotate groups across waves
        const int b  = bc / C;
        const int ch = bc % C;

        __shared__ __align__(16) float sx[T + 8];   // 344, multiple of 4
        __shared__ __align__(16) float sw[168];
        __shared__ float red[8];

        // ---- inline normalization (one pass: sum + sumsq) ----
        const float* xrow = x + (size_t)b * T * C + ch;   // stride C over t
        float vals[3];
        float s = 0.f, ss = 0.f;
        #pragma unroll
        for (int i = 0; i < 3; i++) {
            int t = tid + i * 128;
            float v = (t < T) ? xrow[(size_t)t * C] : 0.f;
            vals[i] = v;
            s += v;
            ss += v * v;
        }
        #pragma unroll
        for (int o = 16; o > 0; o >>= 1) {
            s  += __shfl_xor_sync(0xffffffffu, s, o);
            ss += __shfl_xor_sync(0xffffffffu, ss, o);
        }
        if ((tid & 31) == 0) { red[tid >> 5] = s; red[4 + (tid >> 5)] = ss; }
        __syncthreads();
        const float stot  = red[0] + red[1] + red[2] + red[3];
        const float sstot = red[4] + red[5] + red[6] + red[7];
        const float mu  = stot * (1.0f / (float)T);
        const float var = (sstot - (float)T * mu * mu) * (1.0f / (float)(T - 1));
        const float inv = 1.0f / (sqrtf(fmaxf(var, 0.f)) + 1e-8f);

        #pragma unroll
        for (int i = 0; i < 3; i++) {
            int t = tid + i * 128;
            if (t < T) sx[t] = (vals[i] - mu) * inv;
        }
        if (tid < 8) sx[T + tid] = 0.f;   // pad for vector overread

        // ---- load the single shapelet row (nn, ch) of group g ----
        const float* wg;
        int L;
        switch (g) {
            case 0:  L = 34;  wg = w0; break;
            case 1:  L = 68;  wg = w1; break;
            case 2:  L = 101; wg = w2; break;
            default: L = 168; wg = w3; break;
        }
        const float* wrow = wg + (size_t)(nn * C + ch) * L;
        if (tid < L) sw[tid] = wrow[tid];
        if (tid + 128 < L) sw[tid + 128] = wrow[tid + 128];
        __syncthreads();

        float dmin;
        switch (g) {
            case 0:  dmin = sliding_min4<34>(sx, sw, tid, red); break;   // tw=303
            case 1:  dmin = sliding_min4<68>(sx, sw, tid, red); break;   // tw=269
            case 2:  dmin = sliding_min4<101>(sx, sw, tid, red); break;  // tw=236
            default: dmin = sliding_min4<168>(sx, sw, tid, red); break;  // tw=169
        }

        if (tid == 0) {
            const int idx = b * NF + g * (NSH * C) + nn * C + ch;
            d_out[OFF_DIST + idx] = dmin;
            d_out[OFF_PROB + idx] = expf(-dmin * dmin);   // EPS_GATE = 1
            __threadfence();
            atomicAdd(&g_ctr, 1);        // publish this block's result
        }
    } else {
        // ================= HEAD =================
        const int h = bid - NWORK;       // 0..20

        if (tid == 0) {
            while (atomicAdd(&g_ctr, 0) < NWORK) __nanosleep(64);
        }
        __syncthreads();
        __threadfence();                  // acquire published probs

        if (h < 20) {
            // 16 dots per block; warp w does 4 dots
            const int w  = tid >> 5;
            const int ln = tid & 31;
            const float* probs = d_out + OFF_PROB;
            #pragma unroll
            for (int d = 0; d < 4; d++) {
                const int dot = h * 16 + w * 4 + d;     // < 320
                const int b = dot / OUTC;
                const int o = dot % OUTC;
                const float* p  = probs + b * NF;
                const float* wv = Wout + o * NF;
                float v = 0.f;
                #pragma unroll
                for (int f = ln; f < NF; f += 32) v += p[f] * wv[f];
                #pragma unroll
                for (int off = 16; off > 0; off >>= 1)
                    v += __shfl_xor_sync(0xffffffffu, v, off);
                if (ln == 0) d_out[OFF_OUT + dot] = v;
            }
        } else {
            // loss = 0.1 * mean|Wout|
            __shared__ float sred[4];
            float v = 0.f;
            #pragma unroll
            for (int i = tid; i < OUTC * NF; i += 128) v += fabsf(Wout[i]);
            #pragma unroll
            for (int off = 16; off > 0; off >>= 1)
                v += __shfl_xor_sync(0xffffffffu, v, off);
            if ((tid & 31) == 0) sred[tid >> 5] = v;
            __syncthreads();
            if (tid == 0) {
                float tot = sred[0] + sred[1] + sred[2] + sred[3];
                d_out[OFF_LOSS] = 0.1f * tot / (float)(OUTC * NF);
            }
        }

        __syncthreads();
        if (tid == 0) {
            int v = atomicAdd(&g_ctr2, 1);
            if (v == NHEAD - 1) {
                // last head block resets counters for the next graph replay
                atomicExch(&g_ctr, 0);
                atomicExch(&g_ctr2, 0);
            }
        }
    }
}

// ---------------------------------------------------------------------------
extern "C" void kernel_launch(void* const* d_in, const int* in_sizes, int n_in,
                              void* d_out, int out_size) {
    const float* x    = (const float*)d_in[0];
    const float* w0   = (const float*)d_in[1];
    const float* w1   = (const float*)d_in[2];
    const float* w2   = (const float*)d_in[3];
    const float* w3   = (const float*)d_in[4];
    const float* Wout = (const float*)d_in[5];
    float* out = (float*)d_out;

    fused_kernel<<<NWORK + NHEAD, 128>>>(x, w0, w1, w2, w3, Wout, out);
}

// round 7
// speedup vs baseline: 1.4467x; 1.2733x over previous
#include <cuda_runtime.h>
#include <math_constants.h>

#define B    32
#define T    336
#define C    7
#define NSH  5
#define NG   4
#define NF   140            // 4 groups * 5 * 7
#define OUTC 10
#define NWORKBLK (B * C * NSH)     // 1120 worker blocks (bc, nn); 4 warps = 4 g's
#define NWARPS   (B * C * NG * NSH) // 4480 warp work items
#define NHEAD    21                 // 20 dot blocks + 1 loss block

// offsets in d_out (floats): out[320] | dists[4480] | probs[4480] | loss[1]
#define OFF_OUT   0
#define OFF_DIST  320
#define OFF_PROB  (320 + B*NF)
#define OFF_LOSS  (320 + 2*B*NF)

__device__ int g_ctr  = 0;   // worker warps completed
__device__ int g_ctr2 = 0;   // head blocks completed

// ---------------------------------------------------------------------------
// One warp computes min over all windows for one (bc, g, nn).
// Lane ll owns M window-pairs starting at min(2*ll + 64*m, TW-2).
// Rolling pair (r0,r1): 1 LDS feeds 2 windows (4 FADD) per l-step per m.
// Clamped bases duplicate valid windows -> min unaffected, no guards.
// ---------------------------------------------------------------------------
template<int L, int M>
__device__ __forceinline__ float warp_sliding(const float* __restrict__ sx,
                                              const float* __restrict__ swg,
                                              int ll) {
    constexpr int TW = T - L + 1;
    int   base[M];
    float a0[M], a1[M], r0[M], r1[M];
    #pragma unroll
    for (int m = 0; m < M; m++) {
        int bb = 2 * ll + 64 * m;
        if (bb > TW - 2) bb = TW - 2;
        base[m] = bb;
        a0[m] = 0.f; a1[m] = 0.f;
        r0[m] = sx[bb]; r1[m] = sx[bb + 1];
    }
    #pragma unroll 4
    for (int l = 0; l < L; l++) {
        const float wv = swg[l];                 // broadcast
        #pragma unroll
        for (int m = 0; m < M; m++) {
            a0[m] += fabsf(r0[m] - wv);
            a1[m] += fabsf(r1[m] - wv);
            r0[m] = r1[m];
            r1[m] = sx[base[m] + 2 + l];         // one new value / pair / step
        }
    }
    float mn = CUDART_INF_F;
    #pragma unroll
    for (int m = 0; m < M; m++) mn = fminf(mn, fminf(a0[m], a1[m]));
    #pragma unroll
    for (int o = 16; o > 0; o >>= 1)
        mn = fminf(mn, __shfl_xor_sync(0xffffffffu, mn, o));
    return mn * (1.0f / (float)L);
}

// sw row offsets (16B aligned): g0@0(len34) g1@36(68) g2@104(101) g3@208(168)
#define SW_TOT 376

// ---------------------------------------------------------------------------
// Single launch. grid.x = 1120 workers + 21 head blocks, 128 threads.
// ---------------------------------------------------------------------------
__global__ __launch_bounds__(128, 8) void fused_kernel(
        const float* __restrict__ x,
        const float* __restrict__ w0,
        const float* __restrict__ w1,
        const float* __restrict__ w2,
        const float* __restrict__ w3,
        const float* __restrict__ Wout,
        float* __restrict__ d_out) {
    const int bid = blockIdx.x;
    const int tid = threadIdx.x;          // 128

    if (bid < NWORKBLK) {
        // ================= WORKER =================
        const int nn = bid % NSH;
        const int bc = bid / NSH;
        const int b  = bc / C;
        const int ch = bc % C;
        const int wp = tid >> 5;             // warp 0..3
        const int ll = tid & 31;
        const int g  = (wp + bid) & 3;       // rotate g across blocks/SMSPs

        __shared__ __align__(16) float sx[T + 8];
        __shared__ __align__(16) float sw[SW_TOT];
        __shared__ float red[8];

        // ---- normalization: one pass sum + sumsq over the (b,ch) row ----
        const float* xrow = x + (size_t)b * T * C + ch;   // stride C over t
        float vals[3];
        float s = 0.f, ss = 0.f;
        #pragma unroll
        for (int i = 0; i < 3; i++) {
            int t = tid + i * 128;
            float v = (t < T) ? xrow[(size_t)t * C] : 0.f;
            vals[i] = v;
            s += v;
            ss += v * v;
        }
        #pragma unroll
        for (int o = 16; o > 0; o >>= 1) {
            s  += __shfl_xor_sync(0xffffffffu, s, o);
            ss += __shfl_xor_sync(0xffffffffu, ss, o);
        }
        if (ll == 0) { red[wp] = s; red[4 + wp] = ss; }

        // ---- each warp loads its own shapelet row meanwhile ----
        int L, goff;
        const float* wg;
        switch (g) {
            case 0:  L = 34;  goff = 0;   wg = w0; break;
            case 1:  L = 68;  goff = 36;  wg = w1; break;
            case 2:  L = 101; goff = 104; wg = w2; break;
            default: L = 168; goff = 208; wg = w3; break;
        }
        const float* wrow = wg + (size_t)(nn * C + ch) * L;
        for (int i = ll; i < L; i += 32) sw[goff + i] = wrow[i];

        __syncthreads();
        const float stot  = red[0] + red[1] + red[2] + red[3];
        const float sstot = red[4] + red[5] + red[6] + red[7];
        const float mu  = stot * (1.0f / (float)T);
        const float var = (sstot - (float)T * mu * mu) * (1.0f / (float)(T - 1));
        const float inv = 1.0f / (sqrtf(fmaxf(var, 0.f)) + 1e-8f);

        #pragma unroll
        for (int i = 0; i < 3; i++) {
            int t = tid + i * 128;
            if (t < T) sx[t] = (vals[i] - mu) * inv;
        }
        if (tid < 8) sx[T + tid] = 0.f;   // pad: last rolling load touches sx[T]
        __syncthreads();

        // ---- per-warp sliding min ----
        float dmin;
        switch (g) {
            case 0:  dmin = warp_sliding<34, 5>(sx, sw + 0,   ll); break; // tw=303
            case 1:  dmin = warp_sliding<68, 5>(sx, sw + 36,  ll); break; // tw=269
            case 2:  dmin = warp_sliding<101,4>(sx, sw + 104, ll); break; // tw=236
            default: dmin = warp_sliding<168,3>(sx, sw + 208, ll); break; // tw=169
        }

        if (ll == 0) {
            const int idx = b * NF + g * (NSH * C) + nn * C + ch;
            d_out[OFF_DIST + idx] = dmin;
            d_out[OFF_PROB + idx] = expf(-dmin * dmin);   // EPS_GATE = 1
            __threadfence();
            atomicAdd(&g_ctr, 1);        // publish this warp's result
        }
    } else {
        // ================= HEAD =================
        const int h = bid - NWORKBLK;    // 0..20

        if (tid == 0) {
            while (atomicAdd(&g_ctr, 0) < NWARPS) __nanosleep(64);
        }
        __syncthreads();
        __threadfence();                  // acquire published probs

        if (h < 20) {
            // 16 dots per block; warp wp does 4 dots
            const int wp = tid >> 5;
            const int ln = tid & 31;
            const float* probs = d_out + OFF_PROB;
            #pragma unroll
            for (int d = 0; d < 4; d++) {
                const int dot = h * 16 + wp * 4 + d;     // < 320
                const int b = dot / OUTC;
                const int o = dot % OUTC;
                const float* p  = probs + b * NF;
                const float* wv = Wout + o * NF;
                float v = 0.f;
                #pragma unroll
                for (int f = ln; f < NF; f += 32) v += p[f] * wv[f];
                #pragma unroll
                for (int off = 16; off > 0; off >>= 1)
                    v += __shfl_xor_sync(0xffffffffu, v, off);
                if (ln == 0) d_out[OFF_OUT + dot] = v;
            }
        } else {
            // loss = 0.1 * mean|Wout|
            __shared__ float sred[4];
            float v = 0.f;
            #pragma unroll
            for (int i = tid; i < OUTC * NF; i += 128) v += fabsf(Wout[i]);
            #pragma unroll
            for (int off = 16; off > 0; off >>= 1)
                v += __shfl_xor_sync(0xffffffffu, v, off);
            if ((tid & 31) == 0) sred[tid >> 5] = v;
            __syncthreads();
            if (tid == 0) {
                float tot = sred[0] + sred[1] + sred[2] + sred[3];
                d_out[OFF_LOSS] = 0.1f * tot / (float)(OUTC * NF);
            }
        }

        __syncthreads();
        if (tid == 0) {
            int v = atomicAdd(&g_ctr2, 1);
            if (v == NHEAD - 1) {
                // last head block resets counters for the next graph replay
                atomicExch(&g_ctr, 0);
                atomicExch(&g_ctr2, 0);
            }
        }
    }
}

// ---------------------------------------------------------------------------
extern "C" void kernel_launch(void* const* d_in, const int* in_sizes, int n_in,
                              void* d_out, int out_size) {
    const float* x    = (const float*)d_in[0];
    const float* w0   = (const float*)d_in[1];
    const float* w1   = (const float*)d_in[2];
    const float* w2   = (const float*)d_in[3];
    const float* w3   = (const float*)d_in[4];
    const float* Wout = (const float*)d_in[5];
    float* out = (float*)d_out;

    fused_kernel<<<NWORKBLK + NHEAD, 128>>>(x, w0, w1, w2, w3, Wout, out);
}